// round 6
// baseline (speedup 1.0000x reference)
#include <cuda_runtime.h>
#include <cstdint>

#define HID 64
#define MAX_NODES 100000

// Scratch (persistent across graph replays -> re-initialized each launch)
__device__ float g_m[(size_t)MAX_NODES * HID];    // relu(x @ W^T + b)
__device__ float g_agg[(size_t)MAX_NODES * HID];  // segment-sum accumulator

// ---------------------------------------------------------------------------
// K1: m = relu(x @ W^T + b), and zero g_agg (coalesced).
// 128 threads/block, each lane computes TWO node rows (all 64 cols) in
// 32 float4 register accumulators -> each smem W read serves 2x FMAs,
// halving smem delivered-bytes (the R5 bottleneck).
// ---------------------------------------------------------------------------
__global__ __launch_bounds__(128) void k1_gemm_relu(
    const float* __restrict__ x, const float* __restrict__ W,
    const float* __restrict__ b, float* __restrict__ m,
    float* __restrict__ agg, int n_nodes)
{
    __shared__ float WT[HID * HID];   // WT[d*64 + k] = W[k*64 + d]

    const int tid = threadIdx.x;
    const int node0 = blockIdx.x * 256;      // block covers 256 nodes

    // Transpose W into smem (coalesced global reads)
    #pragma unroll
    for (int i = tid; i < HID * HID; i += 128) {
        int k = i >> 6, d = i & 63;
        WT[d * HID + k] = W[i];
    }

    // Zero agg tile (coalesced)
    {
        size_t lim = (size_t)n_nodes * HID;
        size_t base = (size_t)node0 * HID;
        #pragma unroll
        for (int i = tid; i < 256 * HID; i += 128) {
            size_t idx = base + i;
            if (idx < lim) agg[idx] = 0.0f;
        }
    }
    __syncthreads();

    const int nA = node0 + tid;          // first node
    const int nB = node0 + 128 + tid;    // second node
    const bool hasA = (nA < n_nodes);
    const bool hasB = (nB < n_nodes);
    if (!hasA) return;

    const float4* __restrict__ WT4 = reinterpret_cast<const float4*>(WT);
    const float4* __restrict__ xA =
        reinterpret_cast<const float4*>(x + (size_t)nA * HID);
    const float4* __restrict__ xB =
        reinterpret_cast<const float4*>(x + (size_t)nB * HID);
    const float4* __restrict__ b4 = reinterpret_cast<const float4*>(b);

    float4 accA[16], accB[16];
    #pragma unroll
    for (int j = 0; j < 16; j++) {
        float4 bv = __ldg(&b4[j]);
        accA[j] = bv;
        accB[j] = bv;
    }

    #pragma unroll 1
    for (int dc = 0; dc < 16; dc++) {
        float4 xa4 = __ldg(&xA[dc]);
        float4 xb4 = hasB ? __ldg(&xB[dc]) : make_float4(0.f, 0.f, 0.f, 0.f);
        float xa[4] = {xa4.x, xa4.y, xa4.z, xa4.w};
        float xb[4] = {xb4.x, xb4.y, xb4.z, xb4.w};
        #pragma unroll
        for (int r = 0; r < 4; r++) {
            const int d = dc * 4 + r;
            const float sa = xa[r];
            const float sb = xb[r];
            #pragma unroll
            for (int j = 0; j < 16; j++) {
                float4 w = WT4[d * 16 + j];   // one LDS.128 feeds 8 FMAs
                accA[j].x = fmaf(sa, w.x, accA[j].x);
                accA[j].y = fmaf(sa, w.y, accA[j].y);
                accA[j].z = fmaf(sa, w.z, accA[j].z);
                accA[j].w = fmaf(sa, w.w, accA[j].w);
                accB[j].x = fmaf(sb, w.x, accB[j].x);
                accB[j].y = fmaf(sb, w.y, accB[j].y);
                accB[j].z = fmaf(sb, w.z, accB[j].z);
                accB[j].w = fmaf(sb, w.w, accB[j].w);
            }
        }
    }

    float4* __restrict__ mA = reinterpret_cast<float4*>(m + (size_t)nA * HID);
    #pragma unroll
    for (int j = 0; j < 16; j++) {
        float4 v = accA[j];
        v.x = fmaxf(v.x, 0.f); v.y = fmaxf(v.y, 0.f);
        v.z = fmaxf(v.z, 0.f); v.w = fmaxf(v.w, 0.f);
        mA[j] = v;
    }
    if (hasB) {
        float4* __restrict__ mB = reinterpret_cast<float4*>(m + (size_t)nB * HID);
        #pragma unroll
        for (int j = 0; j < 16; j++) {
            float4 v = accB[j];
            v.x = fmaxf(v.x, 0.f); v.y = fmaxf(v.y, 0.f);
            v.z = fmaxf(v.z, 0.f); v.w = fmaxf(v.w, 0.f);
            mB[j] = v;
        }
    }
}

// ---------------------------------------------------------------------------
// K2: agg[dst] += m[src] over edges. Thread = (edge, quad of 4 cols).
// red.global.add.v4.f32 (no return) quarters the atomic-op count.
// ---------------------------------------------------------------------------
__global__ __launch_bounds__(256) void k2_scatter(
    const int* __restrict__ edges, const float* __restrict__ m,
    float* __restrict__ agg, int n_edges)
{
    long long t = (long long)blockIdx.x * blockDim.x + threadIdx.x;
    int e = (int)(t >> 4);
    if (e >= n_edges) return;
    int q = (int)(t & 15);

    int dst = __ldg(&edges[e]);             // edges[0][e]
    int src = __ldg(&edges[n_edges + e]);   // edges[1][e]

    float4 v = *reinterpret_cast<const float4*>(&m[(size_t)src * HID + q * 4]);
    if (v.x == 0.f && v.y == 0.f && v.z == 0.f && v.w == 0.f) return;  // ReLU zeros

    float* p = &agg[(size_t)dst * HID + q * 4];
    asm volatile("red.global.add.v4.f32 [%0], {%1, %2, %3, %4};"
                 :: "l"(p), "f"(v.x), "f"(v.y), "f"(v.z), "f"(v.w)
                 : "memory");
}

// ---------------------------------------------------------------------------
// K3: out = norm_weight * ((x + agg) * rsqrt(mean((x+agg)^2) + eps)) + norm_bias
// Warp per node, float2 per lane, shfl reduction.
// ---------------------------------------------------------------------------
__global__ __launch_bounds__(256) void k3_rmsnorm(
    const float* __restrict__ x, const float* __restrict__ agg,
    const float* __restrict__ nw, const float* __restrict__ nb,
    float* __restrict__ out, int n_nodes)
{
    int warp = (int)(((long long)blockIdx.x * blockDim.x + threadIdx.x) >> 5);
    int lane = threadIdx.x & 31;
    if (warp >= n_nodes) return;

    size_t base = (size_t)warp * HID + lane * 2;
    float2 xv = *reinterpret_cast<const float2*>(&x[base]);
    float2 av = *reinterpret_cast<const float2*>(&agg[base]);
    float hx = xv.x + av.x;
    float hy = xv.y + av.y;

    float s = hx * hx + hy * hy;
    #pragma unroll
    for (int o = 16; o; o >>= 1) s += __shfl_xor_sync(0xFFFFFFFFu, s, o);

    float inv = rsqrtf(s * (1.0f / 64.0f) + 1e-5f);

    float2 w  = *reinterpret_cast<const float2*>(&nw[lane * 2]);
    float2 bb = *reinterpret_cast<const float2*>(&nb[lane * 2]);
    float2 o2;
    o2.x = fmaf(w.x, hx * inv, bb.x);
    o2.y = fmaf(w.y, hy * inv, bb.y);
    *reinterpret_cast<float2*>(&out[base]) = o2;
}

// ---------------------------------------------------------------------------
extern "C" void kernel_launch(void* const* d_in, const int* in_sizes, int n_in,
                              void* d_out, int out_size)
{
    const float* x  = (const float*)d_in[0];
    const int*   ed = (const int*)  d_in[1];
    const float* W  = (const float*)d_in[2];
    const float* b  = (const float*)d_in[3];
    const float* nw = (const float*)d_in[4];
    const float* nb = (const float*)d_in[5];
    float* out = (float*)d_out;

    const int n_nodes = in_sizes[0] / HID;
    const int n_edges = in_sizes[1] / 2;

    float* m_buf;
    float* agg_buf;
    cudaGetSymbolAddress((void**)&m_buf,   g_m);
    cudaGetSymbolAddress((void**)&agg_buf, g_agg);

    // K1: GEMM+ReLU + zero agg (256 nodes per 128-thread block)
    {
        int blocks = (n_nodes + 255) / 256;
        k1_gemm_relu<<<blocks, 128>>>(x, W, b, m_buf, agg_buf, n_nodes);
    }
    // K2: edge scatter via vector red
    {
        long long threads = (long long)n_edges * 16;
        int blocks = (int)((threads + 255) / 256);
        k2_scatter<<<blocks, 256>>>(ed, m_buf, agg_buf, n_edges);
    }
    // K3: residual + RMSNorm
    {
        long long threads = (long long)n_nodes * 32;
        int blocks = (int)((threads + 255) / 256);
        k3_rmsnorm<<<blocks, 256>>>(x, agg_buf, nw, nb, out, n_nodes);
    }
}

// round 9
// speedup vs baseline: 1.2485x; 1.2485x over previous
#include <cuda_runtime.h>
#include <cstdint>

#define HID 64
#define MAX_NODES 100000
#define MAX_EDGES 1600000
#define SCAN_BLK 1024

// Persistent scratch (re-initialized every launch where needed)
__device__ float g_m[(size_t)MAX_NODES * HID];       // relu(x @ W^T + b)
__device__ int   g_cnt[MAX_NODES];                    // in-degree histogram
__device__ int   g_cur[MAX_NODES];                    // placement cursors
__device__ int   g_loc[MAX_NODES];                    // block-local exclusive scan
__device__ int   g_bsum[128];                         // per-scan-block totals
__device__ int   g_bpref[128];                        // exclusive scan of block totals
__device__ int   g_ssrc[MAX_EDGES];                   // src ids sorted by dst

// ---------------------------------------------------------------------------
// K1: m = relu(x @ W^T + b); also zero cnt + cur.
// 128 threads/block, each lane computes TWO node rows in 32 float4 accs.
// ---------------------------------------------------------------------------
__global__ __launch_bounds__(128) void k1_gemm_relu(
    const float* __restrict__ x, const float* __restrict__ W,
    const float* __restrict__ b, float* __restrict__ m,
    int* __restrict__ cnt, int* __restrict__ cur, int n_nodes)
{
    __shared__ float WT[HID * HID];   // WT[d*64 + k] = W[k*64 + d]

    const int tid = threadIdx.x;
    const int node0 = blockIdx.x * 256;

    #pragma unroll
    for (int i = tid; i < HID * HID; i += 128) {
        int k = i >> 6, d = i & 63;
        WT[d * HID + k] = W[i];
    }

    // Zero counters (grid-strided)
    for (int i = blockIdx.x * 128 + tid; i < n_nodes; i += gridDim.x * 128) {
        cnt[i] = 0;
        cur[i] = 0;
    }
    __syncthreads();

    const int nA = node0 + tid;
    const int nB = node0 + 128 + tid;
    const bool hasB = (nB < n_nodes);
    if (nA >= n_nodes) return;

    const float4* __restrict__ WT4 = reinterpret_cast<const float4*>(WT);
    const float4* __restrict__ xA = reinterpret_cast<const float4*>(x + (size_t)nA * HID);
    const float4* __restrict__ xB = reinterpret_cast<const float4*>(x + (size_t)nB * HID);
    const float4* __restrict__ b4 = reinterpret_cast<const float4*>(b);

    float4 accA[16], accB[16];
    #pragma unroll
    for (int j = 0; j < 16; j++) {
        float4 bv = __ldg(&b4[j]);
        accA[j] = bv; accB[j] = bv;
    }

    #pragma unroll 1
    for (int dc = 0; dc < 16; dc++) {
        float4 xa4 = __ldg(&xA[dc]);
        float4 xb4 = hasB ? __ldg(&xB[dc]) : make_float4(0.f, 0.f, 0.f, 0.f);
        float xa[4] = {xa4.x, xa4.y, xa4.z, xa4.w};
        float xb[4] = {xb4.x, xb4.y, xb4.z, xb4.w};
        #pragma unroll
        for (int r = 0; r < 4; r++) {
            const int d = dc * 4 + r;
            const float sa = xa[r];
            const float sb = xb[r];
            #pragma unroll
            for (int j = 0; j < 16; j++) {
                float4 w = WT4[d * 16 + j];
                accA[j].x = fmaf(sa, w.x, accA[j].x);
                accA[j].y = fmaf(sa, w.y, accA[j].y);
                accA[j].z = fmaf(sa, w.z, accA[j].z);
                accA[j].w = fmaf(sa, w.w, accA[j].w);
                accB[j].x = fmaf(sb, w.x, accB[j].x);
                accB[j].y = fmaf(sb, w.y, accB[j].y);
                accB[j].z = fmaf(sb, w.z, accB[j].z);
                accB[j].w = fmaf(sb, w.w, accB[j].w);
            }
        }
    }

    float4* __restrict__ mA = reinterpret_cast<float4*>(m + (size_t)nA * HID);
    #pragma unroll
    for (int j = 0; j < 16; j++) {
        float4 v = accA[j];
        v.x = fmaxf(v.x, 0.f); v.y = fmaxf(v.y, 0.f);
        v.z = fmaxf(v.z, 0.f); v.w = fmaxf(v.w, 0.f);
        mA[j] = v;
    }
    if (hasB) {
        float4* __restrict__ mB = reinterpret_cast<float4*>(m + (size_t)nB * HID);
        #pragma unroll
        for (int j = 0; j < 16; j++) {
            float4 v = accB[j];
            v.x = fmaxf(v.x, 0.f); v.y = fmaxf(v.y, 0.f);
            v.z = fmaxf(v.z, 0.f); v.w = fmaxf(v.w, 0.f);
            mB[j] = v;
        }
    }
}

// ---------------------------------------------------------------------------
// H: in-degree histogram.
// ---------------------------------------------------------------------------
__global__ __launch_bounds__(256) void k_hist(
    const int* __restrict__ edges, int* __restrict__ cnt, int n_edges)
{
    int e = blockIdx.x * blockDim.x + threadIdx.x;
    if (e >= n_edges) return;
    atomicAdd(&cnt[__ldg(&edges[e])], 1);   // no return use -> RED
}

// ---------------------------------------------------------------------------
// S1: per-block (1024-wide) exclusive scan of cnt -> loc; block totals -> bsum.
// ---------------------------------------------------------------------------
__global__ __launch_bounds__(SCAN_BLK) void k_scan1(
    const int* __restrict__ cnt, int* __restrict__ loc,
    int* __restrict__ bsum, int n)
{
    __shared__ int wtot[32];
    const int tid = threadIdx.x;
    const int lane = tid & 31, wid = tid >> 5;
    const int i = blockIdx.x * SCAN_BLK + tid;

    int v = (i < n) ? cnt[i] : 0;
    int s = v;
    #pragma unroll
    for (int o = 1; o < 32; o <<= 1) {
        int t = __shfl_up_sync(0xFFFFFFFFu, s, o);
        if (lane >= o) s += t;
    }
    if (lane == 31) wtot[wid] = s;
    __syncthreads();
    if (wid == 0) {
        int t = wtot[lane];
        #pragma unroll
        for (int o = 1; o < 32; o <<= 1) {
            int u = __shfl_up_sync(0xFFFFFFFFu, t, o);
            if (lane >= o) t += u;
        }
        wtot[lane] = t;
    }
    __syncthreads();
    int wpref = (wid > 0) ? wtot[wid - 1] : 0;
    int incl = s + wpref;
    if (i < n) loc[i] = incl - v;              // exclusive
    if (tid == SCAN_BLK - 1) bsum[blockIdx.x] = incl;  // block total
}

// ---------------------------------------------------------------------------
// S2: exclusive scan of block totals (<=128 entries), single block.
// ---------------------------------------------------------------------------
__global__ __launch_bounds__(128) void k_scan2(
    const int* __restrict__ bsum, int* __restrict__ bpref, int nb)
{
    __shared__ int wtot[4];
    const int tid = threadIdx.x;
    const int lane = tid & 31, wid = tid >> 5;

    int v = (tid < nb) ? bsum[tid] : 0;
    int s = v;
    #pragma unroll
    for (int o = 1; o < 32; o <<= 1) {
        int t = __shfl_up_sync(0xFFFFFFFFu, s, o);
        if (lane >= o) s += t;
    }
    if (lane == 31) wtot[wid] = s;
    __syncthreads();
    int wpref = 0;
    for (int w = 0; w < wid; w++) wpref += wtot[w];
    if (tid < nb) bpref[tid] = s + wpref - v;   // exclusive
}

// ---------------------------------------------------------------------------
// P: place each edge's src into the dst-sorted array.
// ---------------------------------------------------------------------------
__global__ __launch_bounds__(256) void k_place(
    const int* __restrict__ edges, const int* __restrict__ loc,
    const int* __restrict__ bpref, int* __restrict__ cur,
    int* __restrict__ ssrc, int n_edges)
{
    int e = blockIdx.x * blockDim.x + threadIdx.x;
    if (e >= n_edges) return;
    int dst = __ldg(&edges[e]);
    int src = __ldg(&edges[n_edges + e]);
    int w = atomicAdd(&cur[dst], 1);
    int slot = __ldg(&loc[dst]) + __ldg(&bpref[dst >> 10]) + w;
    ssrc[slot] = src;
}

// ---------------------------------------------------------------------------
// G: per-dst gather of m rows + residual + RMSNorm (fused, replaces K2+K3).
// Warp per node; lane owns 2 columns (float2).
// ---------------------------------------------------------------------------
__global__ __launch_bounds__(256) void k_gather_norm(
    const float* __restrict__ x, const float* __restrict__ m,
    const int* __restrict__ cnt, const int* __restrict__ loc,
    const int* __restrict__ bpref, const int* __restrict__ ssrc,
    const float* __restrict__ nw, const float* __restrict__ nb,
    float* __restrict__ out, int n_nodes)
{
    int node = (int)(((long long)blockIdx.x * blockDim.x + threadIdx.x) >> 5);
    int lane = threadIdx.x & 31;
    if (node >= n_nodes) return;

    const int deg  = __ldg(&cnt[node]);
    const int base = __ldg(&loc[node]) + __ldg(&bpref[node >> 10]);

    float ax = 0.f, ay = 0.f;
    int k = 0;
    while (k < deg) {
        int chunk = min(32, deg - k);
        int my = (lane < chunk) ? __ldg(&ssrc[base + k + lane]) : 0;
        int j = 0;
        #pragma unroll 4
        for (; j < chunk; j++) {
            int s = __shfl_sync(0xFFFFFFFFu, my, j);
            float2 v = *reinterpret_cast<const float2*>(&m[(size_t)s * HID + lane * 2]);
            ax += v.x; ay += v.y;
        }
        k += chunk;
    }

    size_t bofs = (size_t)node * HID + lane * 2;
    float2 xv = *reinterpret_cast<const float2*>(&x[bofs]);
    float hx = xv.x + ax;
    float hy = xv.y + ay;

    float s = hx * hx + hy * hy;
    #pragma unroll
    for (int o = 16; o; o >>= 1) s += __shfl_xor_sync(0xFFFFFFFFu, s, o);
    float inv = rsqrtf(s * (1.0f / 64.0f) + 1e-5f);

    float2 w  = *reinterpret_cast<const float2*>(&nw[lane * 2]);
    float2 bb = *reinterpret_cast<const float2*>(&nb[lane * 2]);
    float2 o2;
    o2.x = fmaf(w.x, hx * inv, bb.x);
    o2.y = fmaf(w.y, hy * inv, bb.y);
    *reinterpret_cast<float2*>(&out[bofs]) = o2;
}

// ---------------------------------------------------------------------------
extern "C" void kernel_launch(void* const* d_in, const int* in_sizes, int n_in,
                              void* d_out, int out_size)
{
    const float* x  = (const float*)d_in[0];
    const int*   ed = (const int*)  d_in[1];
    const float* W  = (const float*)d_in[2];
    const float* b  = (const float*)d_in[3];
    const float* nw = (const float*)d_in[4];
    const float* nb = (const float*)d_in[5];
    float* out = (float*)d_out;

    const int n_nodes = in_sizes[0] / HID;
    const int n_edges = in_sizes[1] / 2;

    float* m_buf; int *cnt, *cur, *loc, *bsum, *bpref, *ssrc;
    cudaGetSymbolAddress((void**)&m_buf, g_m);
    cudaGetSymbolAddress((void**)&cnt,   g_cnt);
    cudaGetSymbolAddress((void**)&cur,   g_cur);
    cudaGetSymbolAddress((void**)&loc,   g_loc);
    cudaGetSymbolAddress((void**)&bsum,  g_bsum);
    cudaGetSymbolAddress((void**)&bpref, g_bpref);
    cudaGetSymbolAddress((void**)&ssrc,  g_ssrc);

    const int nb_scan = (n_nodes + SCAN_BLK - 1) / SCAN_BLK;

    // K1: GEMM+ReLU + zero counters
    k1_gemm_relu<<<(n_nodes + 255) / 256, 128>>>(x, W, b, m_buf, cnt, cur, n_nodes);
    // H: histogram of dst
    k_hist<<<(n_edges + 255) / 256, 256>>>(ed, cnt, n_edges);
    // S1/S2: two-level exclusive scan
    k_scan1<<<nb_scan, SCAN_BLK>>>(cnt, loc, bsum, n_nodes);
    k_scan2<<<1, 128>>>(bsum, bpref, nb_scan);
    // P: dst-sorted edge placement
    k_place<<<(n_edges + 255) / 256, 256>>>(ed, loc, bpref, cur, ssrc, n_edges);
    // G: gather + residual + RMSNorm
    {
        long long threads = (long long)n_nodes * 32;
        int blocks = (int)((threads + 255) / 256);
        k_gather_norm<<<blocks, 256>>>(x, m_buf, cnt, loc, bpref, ssrc, nw, nb, out, n_nodes);
    }
}

// round 10
// speedup vs baseline: 1.5092x; 1.2088x over previous
#include <cuda_runtime.h>
#include <cuda_fp16.h>
#include <cstdint>

#define HID 64
#define MAX_NODES 100000
#define MAX_EDGES 1600000
#define SCAN_BLK 1024

// Persistent scratch (re-initialized every launch where needed)
__device__ __half2 g_m[(size_t)MAX_NODES * (HID / 2)];  // relu(x @ W^T + b), fp16
__device__ int     g_cnt[MAX_NODES];    // in-degree histogram
__device__ int     g_cur[MAX_NODES];    // placement cursors
__device__ int     g_loc[MAX_NODES];    // block-local exclusive scan
__device__ int     g_bsum[128];         // per-scan-block totals
__device__ int     g_bpref[128];        // exclusive scan of block totals
__device__ int     g_ssrc[MAX_EDGES];   // src ids sorted by dst
__device__ int     g_ticket;            // last-block ticket for fused scan

// ---------------------------------------------------------------------------
// Z: zero counters + ticket (side stream, before H/S/P).
// ---------------------------------------------------------------------------
__global__ __launch_bounds__(256) void k_zero(
    int* __restrict__ cnt, int* __restrict__ cur, int n_nodes)
{
    int i = blockIdx.x * 256 + threadIdx.x;
    if (i < n_nodes) { cnt[i] = 0; cur[i] = 0; }
    if (i == 0) g_ticket = 0;
}

// ---------------------------------------------------------------------------
// K1: m = relu(x @ W^T + b)  (fp16 output).
// 128 threads/block, each lane computes TWO node rows in 32 float4 accs.
// ---------------------------------------------------------------------------
__global__ __launch_bounds__(128) void k1_gemm_relu(
    const float* __restrict__ x, const float* __restrict__ W,
    const float* __restrict__ b, __half2* __restrict__ m, int n_nodes)
{
    __shared__ float WT[HID * HID];   // WT[d*64 + k] = W[k*64 + d]

    const int tid = threadIdx.x;
    const int node0 = blockIdx.x * 256;

    #pragma unroll
    for (int i = tid; i < HID * HID; i += 128) {
        int k = i >> 6, d = i & 63;
        WT[d * HID + k] = W[i];
    }
    __syncthreads();

    const int nA = node0 + tid;
    const int nB = node0 + 128 + tid;
    const bool hasB = (nB < n_nodes);
    if (nA >= n_nodes) return;

    const float4* __restrict__ WT4 = reinterpret_cast<const float4*>(WT);
    const float4* __restrict__ xA = reinterpret_cast<const float4*>(x + (size_t)nA * HID);
    const float4* __restrict__ xB = reinterpret_cast<const float4*>(x + (size_t)nB * HID);
    const float4* __restrict__ b4 = reinterpret_cast<const float4*>(b);

    float4 accA[16], accB[16];
    #pragma unroll
    for (int j = 0; j < 16; j++) {
        float4 bv = __ldg(&b4[j]);
        accA[j] = bv; accB[j] = bv;
    }

    #pragma unroll 1
    for (int dc = 0; dc < 16; dc++) {
        float4 xa4 = __ldg(&xA[dc]);
        float4 xb4 = hasB ? __ldg(&xB[dc]) : make_float4(0.f, 0.f, 0.f, 0.f);
        float xa[4] = {xa4.x, xa4.y, xa4.z, xa4.w};
        float xb[4] = {xb4.x, xb4.y, xb4.z, xb4.w};
        #pragma unroll
        for (int r = 0; r < 4; r++) {
            const int d = dc * 4 + r;
            const float sa = xa[r];
            const float sb = xb[r];
            #pragma unroll
            for (int j = 0; j < 16; j++) {
                float4 w = WT4[d * 16 + j];
                accA[j].x = fmaf(sa, w.x, accA[j].x);
                accA[j].y = fmaf(sa, w.y, accA[j].y);
                accA[j].z = fmaf(sa, w.z, accA[j].z);
                accA[j].w = fmaf(sa, w.w, accA[j].w);
                accB[j].x = fmaf(sb, w.x, accB[j].x);
                accB[j].y = fmaf(sb, w.y, accB[j].y);
                accB[j].z = fmaf(sb, w.z, accB[j].z);
                accB[j].w = fmaf(sb, w.w, accB[j].w);
            }
        }
    }

    {
        uint4* __restrict__ mrow = reinterpret_cast<uint4*>(m + (size_t)nA * (HID / 2));
        #pragma unroll
        for (int j = 0; j < 8; j++) {
            float4 v0 = accA[2 * j], v1 = accA[2 * j + 1];
            __half2 h0 = __floats2half2_rn(fmaxf(v0.x, 0.f), fmaxf(v0.y, 0.f));
            __half2 h1 = __floats2half2_rn(fmaxf(v0.z, 0.f), fmaxf(v0.w, 0.f));
            __half2 h2 = __floats2half2_rn(fmaxf(v1.x, 0.f), fmaxf(v1.y, 0.f));
            __half2 h3 = __floats2half2_rn(fmaxf(v1.z, 0.f), fmaxf(v1.w, 0.f));
            uint4 u;
            u.x = *reinterpret_cast<unsigned*>(&h0);
            u.y = *reinterpret_cast<unsigned*>(&h1);
            u.z = *reinterpret_cast<unsigned*>(&h2);
            u.w = *reinterpret_cast<unsigned*>(&h3);
            mrow[j] = u;
        }
    }
    if (hasB) {
        uint4* __restrict__ mrow = reinterpret_cast<uint4*>(m + (size_t)nB * (HID / 2));
        #pragma unroll
        for (int j = 0; j < 8; j++) {
            float4 v0 = accB[2 * j], v1 = accB[2 * j + 1];
            __half2 h0 = __floats2half2_rn(fmaxf(v0.x, 0.f), fmaxf(v0.y, 0.f));
            __half2 h1 = __floats2half2_rn(fmaxf(v0.z, 0.f), fmaxf(v0.w, 0.f));
            __half2 h2 = __floats2half2_rn(fmaxf(v1.x, 0.f), fmaxf(v1.y, 0.f));
            __half2 h3 = __floats2half2_rn(fmaxf(v1.z, 0.f), fmaxf(v1.w, 0.f));
            uint4 u;
            u.x = *reinterpret_cast<unsigned*>(&h0);
            u.y = *reinterpret_cast<unsigned*>(&h1);
            u.z = *reinterpret_cast<unsigned*>(&h2);
            u.w = *reinterpret_cast<unsigned*>(&h3);
            mrow[j] = u;
        }
    }
}

// ---------------------------------------------------------------------------
// H: in-degree histogram.
// ---------------------------------------------------------------------------
__global__ __launch_bounds__(256) void k_hist(
    const int* __restrict__ edges, int* __restrict__ cnt, int n_edges)
{
    int e = blockIdx.x * blockDim.x + threadIdx.x;
    if (e >= n_edges) return;
    atomicAdd(&cnt[__ldg(&edges[e])], 1);
}

// ---------------------------------------------------------------------------
// S: per-block exclusive scan of cnt -> loc; block totals -> bsum;
// fused second level: last-arriving block scans bsum -> bpref.
// ---------------------------------------------------------------------------
__global__ __launch_bounds__(SCAN_BLK) void k_scan(
    const int* __restrict__ cnt, int* __restrict__ loc,
    int* __restrict__ bsum, int* __restrict__ bpref, int n)
{
    __shared__ int wtot[32];
    __shared__ int sh_last;
    const int tid = threadIdx.x;
    const int lane = tid & 31, wid = tid >> 5;
    const int i = blockIdx.x * SCAN_BLK + tid;

    int v = (i < n) ? cnt[i] : 0;
    int s = v;
    #pragma unroll
    for (int o = 1; o < 32; o <<= 1) {
        int t = __shfl_up_sync(0xFFFFFFFFu, s, o);
        if (lane >= o) s += t;
    }
    if (lane == 31) wtot[wid] = s;
    __syncthreads();
    if (wid == 0) {
        int t = wtot[lane];
        #pragma unroll
        for (int o = 1; o < 32; o <<= 1) {
            int u = __shfl_up_sync(0xFFFFFFFFu, t, o);
            if (lane >= o) t += u;
        }
        wtot[lane] = t;
    }
    __syncthreads();
    int wpref = (wid > 0) ? wtot[wid - 1] : 0;
    int incl = s + wpref;
    if (i < n) loc[i] = incl - v;                 // exclusive
    if (tid == SCAN_BLK - 1) {
        bsum[blockIdx.x] = incl;                  // block total
        __threadfence();
    }
    __syncthreads();
    if (tid == 0) {
        __threadfence();
        sh_last = (atomicAdd(&g_ticket, 1) == (int)gridDim.x - 1);
    }
    __syncthreads();
    if (!sh_last) return;                         // uniform per block

    // ---- fused level-2 scan on the last block (nb <= 128) ----
    __syncthreads();
    int bv = 0, bs = 0;
    const int nb = gridDim.x;
    if (tid < 128) {
        bv = (tid < nb) ? bsum[tid] : 0;
        bs = bv;
        #pragma unroll
        for (int o = 1; o < 32; o <<= 1) {
            int t = __shfl_up_sync(0xFFFFFFFFu, bs, o);
            if (lane >= o) bs += t;
        }
        if (lane == 31) wtot[wid] = bs;
    }
    __syncthreads();
    if (tid < 128) {
        int wpref2 = 0;
        for (int w = 0; w < wid; w++) wpref2 += wtot[w];
        if (tid < nb) bpref[tid] = bs + wpref2 - bv;   // exclusive
    }
}

// ---------------------------------------------------------------------------
// P: place each edge's src into the dst-sorted array.
// ---------------------------------------------------------------------------
__global__ __launch_bounds__(256) void k_place(
    const int* __restrict__ edges, const int* __restrict__ loc,
    const int* __restrict__ bpref, int* __restrict__ cur,
    int* __restrict__ ssrc, int n_edges)
{
    int e = blockIdx.x * blockDim.x + threadIdx.x;
    if (e >= n_edges) return;
    int dst = __ldg(&edges[e]);
    int src = __ldg(&edges[n_edges + e]);
    int w = atomicAdd(&cur[dst], 1);
    int slot = __ldg(&loc[dst]) + __ldg(&bpref[dst >> 10]) + w;
    ssrc[slot] = src;
}

// ---------------------------------------------------------------------------
// G: per-dst gather of fp16 m rows + residual + RMSNorm (fp32 accumulate).
// Warp per node; lane owns 2 columns.
// ---------------------------------------------------------------------------
__global__ __launch_bounds__(256) void k_gather_norm(
    const float* __restrict__ x, const __half2* __restrict__ m,
    const int* __restrict__ cnt, const int* __restrict__ loc,
    const int* __restrict__ bpref, const int* __restrict__ ssrc,
    const float* __restrict__ nw, const float* __restrict__ nb,
    float* __restrict__ out, int n_nodes)
{
    int node = (int)(((long long)blockIdx.x * blockDim.x + threadIdx.x) >> 5);
    int lane = threadIdx.x & 31;
    if (node >= n_nodes) return;

    const int deg  = __ldg(&cnt[node]);
    const int base = __ldg(&loc[node]) + __ldg(&bpref[node >> 10]);

    float ax = 0.f, ay = 0.f;
    int k = 0;
    while (k < deg) {
        int chunk = min(32, deg - k);
        int my = (lane < chunk) ? __ldg(&ssrc[base + k + lane]) : 0;
        int j = 0;
        #pragma unroll 4
        for (; j < chunk; j++) {
            int s = __shfl_sync(0xFFFFFFFFu, my, j);
            __half2 v = __ldg(&m[(size_t)s * (HID / 2) + lane]);
            float2 f = __half22float2(v);
            ax += f.x; ay += f.y;
        }
        k += chunk;
    }

    size_t bofs = (size_t)node * HID + lane * 2;
    float2 xv = *reinterpret_cast<const float2*>(&x[bofs]);
    float hx = xv.x + ax;
    float hy = xv.y + ay;

    float s = hx * hx + hy * hy;
    #pragma unroll
    for (int o = 16; o; o >>= 1) s += __shfl_xor_sync(0xFFFFFFFFu, s, o);
    float inv = rsqrtf(s * (1.0f / 64.0f) + 1e-5f);

    float2 w  = *reinterpret_cast<const float2*>(&nw[lane * 2]);
    float2 bb = *reinterpret_cast<const float2*>(&nb[lane * 2]);
    float2 o2;
    o2.x = fmaf(w.x, hx * inv, bb.x);
    o2.y = fmaf(w.y, hy * inv, bb.y);
    *reinterpret_cast<float2*>(&out[bofs]) = o2;
}

// ---------------------------------------------------------------------------
extern "C" void kernel_launch(void* const* d_in, const int* in_sizes, int n_in,
                              void* d_out, int out_size)
{
    const float* x  = (const float*)d_in[0];
    const int*   ed = (const int*)  d_in[1];
    const float* W  = (const float*)d_in[2];
    const float* b  = (const float*)d_in[3];
    const float* nw = (const float*)d_in[4];
    const float* nb = (const float*)d_in[5];
    float* out = (float*)d_out;

    const int n_nodes = in_sizes[0] / HID;
    const int n_edges = in_sizes[1] / 2;

    __half2* m_buf; int *cnt, *cur, *loc, *bsum, *bpref, *ssrc;
    cudaGetSymbolAddress((void**)&m_buf, g_m);
    cudaGetSymbolAddress((void**)&cnt,   g_cnt);
    cudaGetSymbolAddress((void**)&cur,   g_cur);
    cudaGetSymbolAddress((void**)&loc,   g_loc);
    cudaGetSymbolAddress((void**)&bsum,  g_bsum);
    cudaGetSymbolAddress((void**)&bpref, g_bpref);
    cudaGetSymbolAddress((void**)&ssrc,  g_ssrc);

    const int nb_scan = (n_nodes + SCAN_BLK - 1) / SCAN_BLK;

    // Side stream + events: parallel graph branch for edge preprocessing.
    // kernel_launch only runs for correctness + capture (replays don't call it),
    // so per-call handle creation is bounded; no device memory is allocated.
    cudaStream_t side;
    cudaStreamCreateWithFlags(&side, cudaStreamNonBlocking);
    cudaEvent_t evF, evJ;
    cudaEventCreateWithFlags(&evF, cudaEventDisableTiming);
    cudaEventCreateWithFlags(&evJ, cudaEventDisableTiming);

    cudaEventRecord(evF, 0);
    cudaStreamWaitEvent(side, evF, 0);
    k_zero <<<(n_nodes + 255) / 256, 256, 0, side>>>(cnt, cur, n_nodes);
    k_hist <<<(n_edges + 255) / 256, 256, 0, side>>>(ed, cnt, n_edges);
    k_scan <<<nb_scan, SCAN_BLK, 0, side>>>(cnt, loc, bsum, bpref, n_nodes);
    k_place<<<(n_edges + 255) / 256, 256, 0, side>>>(ed, loc, bpref, cur, ssrc, n_edges);
    cudaEventRecord(evJ, side);

    // Main stream: GEMM+ReLU overlaps the side chain
    k1_gemm_relu<<<(n_nodes + 255) / 256, 128>>>(x, W, b, m_buf, n_nodes);

    // Join, then fused gather + residual + RMSNorm
    cudaStreamWaitEvent(0, evJ, 0);
    {
        long long threads = (long long)n_nodes * 32;
        int blocks = (int)((threads + 255) / 256);
        k_gather_norm<<<blocks, 256>>>(x, m_buf, cnt, loc, bpref, ssrc, nw, nb, out, n_nodes);
    }
}